// round 11
// baseline (speedup 1.0000x reference)
#include <cuda_runtime.h>
#include <cuda_fp16.h>
#include <cstdint>
#include <cstddef>

// ---------------- problem constants ----------------
#define TOKENS 8192
#define KDIM   4096
#define ODIM   4096

#define BM 128
#define BN 128
#define BK 64
#define KT (KDIM / BK)      // 64 k-iterations
#define STAGES 4
#define NTHREADS 256        // 8 warps in 2x4, warp tile 64x32

#define A_STAGE_BYTES (BM * BK * 2)
#define B_STAGE_BYTES (BN * BK * 2)
#define STAGE_BYTES   (A_STAGE_BYTES + B_STAGE_BYTES)   // 32768
#define SMEM_TOTAL    (STAGES * STAGE_BYTES)            // 131072 -> 1 CTA/SM

// ---------------- scratch (no runtime allocation allowed) ----------------
__device__ __half g_xh[(size_t)TOKENS * KDIM];   // 64 MB
__device__ __half g_wq[(size_t)ODIM * KDIM];     // 32 MB

// ---------------- helpers ----------------
__device__ __forceinline__ uint32_t smem_to_u32(const void* p) {
    uint32_t a;
    asm("{ .reg .u64 t; cvta.to.shared.u64 t, %1; cvt.u32.u64 %0, t; }" : "=r"(a) : "l"(p));
    return a;
}
__device__ __forceinline__ uint32_t sw128(uint32_t off) {
    return off ^ ((off >> 3) & 0x70);
}
__device__ __forceinline__ void cp_async16(uint32_t dst, const void* src) {
    asm volatile("cp.async.cg.shared.global [%0], [%1], 16;" :: "r"(dst), "l"(src));
}
__device__ __forceinline__ void cp_commit() {
    asm volatile("cp.async.commit_group;" ::: "memory");
}
template <int N>
__device__ __forceinline__ void cp_wait() {
    asm volatile("cp.async.wait_group %0;" :: "n"(N) : "memory");
}
__device__ __forceinline__ void ldsm4(uint32_t* r, uint32_t addr) {
    asm volatile("ldmatrix.sync.aligned.m8n8.x4.shared.b16 {%0,%1,%2,%3}, [%4];"
                 : "=r"(r[0]), "=r"(r[1]), "=r"(r[2]), "=r"(r[3]) : "r"(addr));
}
// fp16-accumulate MMA: D(2xb32 = 4 halves) = A*B + C
__device__ __forceinline__ void mma16816h(uint32_t* d, const uint32_t* a,
                                          uint32_t b0, uint32_t b1,
                                          uint32_t c0, uint32_t c1) {
    asm volatile(
        "mma.sync.aligned.m16n8k16.row.col.f16.f16.f16.f16 "
        "{%0,%1}, {%2,%3,%4,%5}, {%6,%7}, {%8,%9};"
        : "=r"(d[0]), "=r"(d[1])
        : "r"(a[0]), "r"(a[1]), "r"(a[2]), "r"(a[3]),
          "r"(b0), "r"(b1), "r"(c0), "r"(c1));
}

// ---------------- fused prep kernel ----------------
// Quantizer: levels {±(L+S), ±(L−S)}, thresholds {−L, 0, L}
// => q = sgn(w) * (L + (|w| > L ? S : -S)).   (ILP = 2 float4 per thread)
#define W_N4   (ODIM * KDIM / 4)
#define X_N4   (TOKENS * KDIM / 4)
#define WBLKS  ((W_N4 / 2 + 255) / 256)
#define XBLKS  ((X_N4 / 2 + 255) / 256)

__global__ void prep_kernel(const float* __restrict__ w,
                            const float* __restrict__ x,
                            const float* __restrict__ basis) {
    int b = blockIdx.x;
    if (b < WBLKS) {
        float b0 = fabsf(basis[0]), b1 = fabsf(basis[1]);
        float L = fmaxf(b0, b1), S = fminf(b0, b1);
        int i0 = (b * blockDim.x + threadIdx.x) * 2;
#pragma unroll
        for (int u = 0; u < 2; u++) {
            int i = i0 + u;
            if (i >= W_N4) return;
            float4 v = reinterpret_cast<const float4*>(w)[i];
            float m0 = L + ((fabsf(v.x) > L) ? S : -S);
            float m1 = L + ((fabsf(v.y) > L) ? S : -S);
            float m2 = L + ((fabsf(v.z) > L) ? S : -S);
            float m3 = L + ((fabsf(v.w) > L) ? S : -S);
            __half2 p0 = __floats2half2_rn(copysignf(m0, v.x), copysignf(m1, v.y));
            __half2 p1 = __floats2half2_rn(copysignf(m2, v.z), copysignf(m3, v.w));
            uint2 o;
            o.x = *reinterpret_cast<uint32_t*>(&p0);
            o.y = *reinterpret_cast<uint32_t*>(&p1);
            reinterpret_cast<uint2*>(g_wq)[i] = o;
        }
    } else {
        int i0 = ((b - WBLKS) * blockDim.x + threadIdx.x) * 2;
#pragma unroll
        for (int u = 0; u < 2; u++) {
            int i = i0 + u;
            if (i >= X_N4) return;
            float4 v = reinterpret_cast<const float4*>(x)[i];
            __half2 a = __floats2half2_rn(v.x, v.y);
            __half2 c = __floats2half2_rn(v.z, v.w);
            uint2 o;
            o.x = *reinterpret_cast<uint32_t*>(&a);
            o.y = *reinterpret_cast<uint32_t*>(&c);
            reinterpret_cast<uint2*>(g_xh)[i] = o;
        }
    }
}

// ---------------- GEMM mainloop ----------------
// 256 threads load one stage: A 1024 + B 1024 16B-chunks -> 8 per thread.
__device__ __forceinline__ void load_stage(uint32_t sb, int s, int kt, int tid,
                                           const __half* gA, const __half* gB) {
    uint32_t a_off = sb + s * STAGE_BYTES;
    uint32_t b_off = a_off + A_STAGE_BYTES;
#pragma unroll
    for (int p = 0; p < 4; p++) {
        int id = tid + p * NTHREADS;
        int row = id >> 3, ch = id & 7;
        uint32_t off = (uint32_t)row * 128 + (uint32_t)ch * 16;
        cp_async16(a_off + sw128(off),
                   gA + (size_t)row * KDIM + kt * BK + ch * 8);
    }
#pragma unroll
    for (int p = 0; p < 4; p++) {
        int id = tid + p * NTHREADS;
        int row = id >> 3, ch = id & 7;
        uint32_t off = (uint32_t)row * 128 + (uint32_t)ch * 16;
        cp_async16(b_off + sw128(off),
                   gB + (size_t)row * KDIM + kt * BK + ch * 8);
    }
    cp_commit();
}

__global__ void __launch_bounds__(NTHREADS, 1)
gemm_kernel(const float* __restrict__ bias, float* __restrict__ out) {
    extern __shared__ char smem[];
    uint32_t sb = smem_to_u32(smem);
    int tid = threadIdx.x;
    int wid = tid >> 5, lane = tid & 31;
    int warp_m = wid >> 2;            // 0..1  (64 rows each)
    int warp_n = wid & 3;             // 0..3  (32 cols each)
    int nbase = blockIdx.x * BN;
    int mbase = blockIdx.y * BM;

    const __half* gA = g_xh + (size_t)mbase * KDIM;
    const __half* gB = g_wq + (size_t)nbase * KDIM;

    float acc[4][4][4];
#pragma unroll
    for (int i = 0; i < 4; i++)
#pragma unroll
        for (int j = 0; j < 4; j++)
#pragma unroll
            for (int r = 0; r < 4; r++) acc[i][j][r] = 0.f;

    // XOR swizzle iterator: address for chunk (ch0 + 2*kk) of a row is
    //   lane_base(row) ^ (kk << 5)     [bits disjoint, no carries]
    int a_row = warp_m * 64 + ((lane >> 3) & 1) * 8 + (lane & 7);
    int b_row = warp_n * 32 + ((lane >> 3) & 1) * 8 + (lane & 7);
    int ch0 = lane >> 4;              // 0..1
    uint32_t a_base0 = (uint32_t)a_row * 128 + 16u * (uint32_t)(ch0 ^ (a_row & 7));
    uint32_t b_base0 = (uint32_t)b_row * 128 + 16u * (uint32_t)(ch0 ^ (b_row & 7));

    // prologue: fill STAGES-1 stages
    load_stage(sb, 0, 0, tid, gA, gB);
    load_stage(sb, 1, 1, tid, gA, gB);
    load_stage(sb, 2, 2, tid, gA, gB);

    uint32_t z = 0;                   // zero C operand for chunk-start MMAs

    int cur = 0, nxt_s = STAGES - 1;
    for (int kt = 0; kt < KT; kt++) {
        cp_wait<STAGES - 2>();
        __syncthreads();

        uint32_t a_base = sb + cur * STAGE_BYTES + a_base0;
        uint32_t b_base = sb + cur * STAGE_BYTES + A_STAGE_BYTES + b_base0;

        int nxt = kt + STAGES - 1;
        if (nxt < KT) load_stage(sb, nxt_s, nxt, tid, gA, gB);
        else cp_commit();

        // f16 accumulation over this BK=64 chunk (4 MMAs deep), then promote.
        uint32_t hacc[4][4][2];
#pragma unroll
        for (int kk = 0; kk < 4; kk++) {
            uint32_t ax = a_base ^ (uint32_t)(kk << 5);
            uint32_t bx = b_base ^ (uint32_t)(kk << 5);
            uint32_t af[4][4];
#pragma unroll
            for (int i = 0; i < 4; i++) ldsm4(af[i], ax + i * 2048);
            uint32_t bf[2][4];
#pragma unroll
            for (int g = 0; g < 2; g++) ldsm4(bf[g], bx + g * 2048);
#pragma unroll
            for (int i = 0; i < 4; i++)
#pragma unroll
                for (int j = 0; j < 4; j++) {
                    uint32_t b0 = bf[j >> 1][j & 1];
                    uint32_t b1 = bf[j >> 1][(j & 1) + 2];
                    if (kk == 0)
                        mma16816h(hacc[i][j], af[i], b0, b1, z, z);
                    else
                        mma16816h(hacc[i][j], af[i], b0, b1,
                                  hacc[i][j][0], hacc[i][j][1]);
                }
        }
        // promote chunk sums into fp32 master accumulators
#pragma unroll
        for (int i = 0; i < 4; i++)
#pragma unroll
            for (int j = 0; j < 4; j++) {
                float2 f01 = __half22float2(
                    *reinterpret_cast<__half2*>(&hacc[i][j][0]));
                float2 f23 = __half22float2(
                    *reinterpret_cast<__half2*>(&hacc[i][j][1]));
                acc[i][j][0] += f01.x; acc[i][j][1] += f01.y;
                acc[i][j][2] += f23.x; acc[i][j][3] += f23.y;
            }

        cur = (cur == STAGES - 1) ? 0 : cur + 1;
        nxt_s = (nxt_s == STAGES - 1) ? 0 : nxt_s + 1;
    }

    // epilogue: direct to gmem with bias
    int m0 = mbase + warp_m * 64 + (lane >> 2);
    int n0 = nbase + warp_n * 32 + (lane & 3) * 2;
    float2 bj[4];
#pragma unroll
    for (int j = 0; j < 4; j++)
        bj[j] = *reinterpret_cast<const float2*>(bias + n0 + j * 8);
#pragma unroll
    for (int i = 0; i < 4; i++) {
        float* row_lo = out + (size_t)(m0 + i * 16) * ODIM;
        float* row_hi = out + (size_t)(m0 + i * 16 + 8) * ODIM;
#pragma unroll
        for (int j = 0; j < 4; j++) {
            float2 lo = { acc[i][j][0] + bj[j].x, acc[i][j][1] + bj[j].y };
            float2 hi = { acc[i][j][2] + bj[j].x, acc[i][j][3] + bj[j].y };
            *reinterpret_cast<float2*>(row_lo + n0 + j * 8) = lo;
            *reinterpret_cast<float2*>(row_hi + n0 + j * 8) = hi;
        }
    }
}

// ---------------- launch ----------------
extern "C" void kernel_launch(void* const* d_in, const int* in_sizes, int n_in,
                              void* d_out, int out_size) {
    const float* x     = (const float*)d_in[0];
    const float* w     = (const float*)d_in[1];
    const float* bias  = (const float*)d_in[2];
    const float* basis = (const float*)d_in[3];
    float* out = (float*)d_out;

    cudaFuncSetAttribute(gemm_kernel, cudaFuncAttributeMaxDynamicSharedMemorySize,
                         SMEM_TOTAL);

    prep_kernel<<<WBLKS + XBLKS, 256>>>(w, x, basis);
    gemm_kernel<<<dim3(ODIM / BN, TOKENS / BM), NTHREADS, SMEM_TOTAL>>>(bias, out);
}

// round 12
// speedup vs baseline: 1.2282x; 1.2282x over previous
#include <cuda_runtime.h>
#include <cuda_fp16.h>
#include <cstdint>
#include <cstddef>

// ---------------- problem constants ----------------
#define TOKENS 8192
#define KDIM   4096
#define ODIM   4096

#define BM 128
#define BN 128
#define BK 64
#define KT (KDIM / BK)      // 64 k-iterations
#define STAGES 3
#define NTHREADS 256        // 8 warps in 2x4, warp tile 64x32

#define A_STAGE_BYTES (BM * BK * 2)
#define B_STAGE_BYTES (BN * BK * 2)
#define STAGE_BYTES   (A_STAGE_BYTES + B_STAGE_BYTES)   // 32768
#define SMEM_TOTAL    (STAGES * STAGE_BYTES)            // 98304 -> 2 CTAs/SM

// ---------------- scratch (no runtime allocation allowed) ----------------
__device__ __half g_xh[(size_t)TOKENS * KDIM];   // 64 MB
__device__ __half g_wq[(size_t)ODIM * KDIM];     // 32 MB

// ---------------- helpers ----------------
__device__ __forceinline__ uint32_t smem_to_u32(const void* p) {
    uint32_t a;
    asm("{ .reg .u64 t; cvta.to.shared.u64 t, %1; cvt.u32.u64 %0, t; }" : "=r"(a) : "l"(p));
    return a;
}
__device__ __forceinline__ uint32_t sw128(uint32_t off) {
    return off ^ ((off >> 3) & 0x70);
}
__device__ __forceinline__ void cp_async16(uint32_t dst, const void* src) {
    asm volatile("cp.async.cg.shared.global [%0], [%1], 16;" :: "r"(dst), "l"(src));
}
__device__ __forceinline__ void cp_commit() {
    asm volatile("cp.async.commit_group;" ::: "memory");
}
template <int N>
__device__ __forceinline__ void cp_wait() {
    asm volatile("cp.async.wait_group %0;" :: "n"(N) : "memory");
}
__device__ __forceinline__ void ldsm4(uint32_t* r, uint32_t addr) {
    asm volatile("ldmatrix.sync.aligned.m8n8.x4.shared.b16 {%0,%1,%2,%3}, [%4];"
                 : "=r"(r[0]), "=r"(r[1]), "=r"(r[2]), "=r"(r[3]) : "r"(addr));
}
__device__ __forceinline__ void mma16816(float* c, const uint32_t* a,
                                         uint32_t b0, uint32_t b1) {
    asm volatile(
        "mma.sync.aligned.m16n8k16.row.col.f32.f16.f16.f32 "
        "{%0,%1,%2,%3}, {%4,%5,%6,%7}, {%8,%9}, {%0,%1,%2,%3};"
        : "+f"(c[0]), "+f"(c[1]), "+f"(c[2]), "+f"(c[3])
        : "r"(a[0]), "r"(a[1]), "r"(a[2]), "r"(a[3]), "r"(b0), "r"(b1));
}

// ---------------- fused prep kernel ----------------
// Quantizer: levels {±(L+S), ±(L−S)}, thresholds {−L, 0, L}
// => q = sgn(w) * (L + (|w| > L ? S : -S)).   (ILP = 2 float4 per thread)
#define W_N4   (ODIM * KDIM / 4)
#define X_N4   (TOKENS * KDIM / 4)
#define WBLKS  ((W_N4 / 2 + 255) / 256)
#define XBLKS  ((X_N4 / 2 + 255) / 256)

__global__ void prep_kernel(const float* __restrict__ w,
                            const float* __restrict__ x,
                            const float* __restrict__ basis) {
    int b = blockIdx.x;
    if (b < WBLKS) {
        float b0 = fabsf(basis[0]), b1 = fabsf(basis[1]);
        float L = fmaxf(b0, b1), S = fminf(b0, b1);
        int i0 = (b * blockDim.x + threadIdx.x) * 2;
#pragma unroll
        for (int u = 0; u < 2; u++) {
            int i = i0 + u;
            if (i >= W_N4) return;
            float4 v = reinterpret_cast<const float4*>(w)[i];
            float m0 = L + ((fabsf(v.x) > L) ? S : -S);
            float m1 = L + ((fabsf(v.y) > L) ? S : -S);
            float m2 = L + ((fabsf(v.z) > L) ? S : -S);
            float m3 = L + ((fabsf(v.w) > L) ? S : -S);
            __half2 p0 = __floats2half2_rn(copysignf(m0, v.x), copysignf(m1, v.y));
            __half2 p1 = __floats2half2_rn(copysignf(m2, v.z), copysignf(m3, v.w));
            uint2 o;
            o.x = *reinterpret_cast<uint32_t*>(&p0);
            o.y = *reinterpret_cast<uint32_t*>(&p1);
            reinterpret_cast<uint2*>(g_wq)[i] = o;
        }
    } else {
        int i0 = ((b - WBLKS) * blockDim.x + threadIdx.x) * 2;
#pragma unroll
        for (int u = 0; u < 2; u++) {
            int i = i0 + u;
            if (i >= X_N4) return;
            float4 v = reinterpret_cast<const float4*>(x)[i];
            __half2 a = __floats2half2_rn(v.x, v.y);
            __half2 c = __floats2half2_rn(v.z, v.w);
            uint2 o;
            o.x = *reinterpret_cast<uint32_t*>(&a);
            o.y = *reinterpret_cast<uint32_t*>(&c);
            reinterpret_cast<uint2*>(g_xh)[i] = o;
        }
    }
}

// ---------------- GEMM mainloop ----------------
__device__ __forceinline__ void load_stage(uint32_t sb, int s, int kt, int tid,
                                           const __half* gA, const __half* gB) {
    uint32_t a_off = sb + s * STAGE_BYTES;
    uint32_t b_off = a_off + A_STAGE_BYTES;
#pragma unroll
    for (int p = 0; p < 4; p++) {
        int id = tid + p * NTHREADS;
        int row = id >> 3, ch = id & 7;
        uint32_t off = (uint32_t)row * 128 + (uint32_t)ch * 16;
        cp_async16(a_off + sw128(off),
                   gA + (size_t)row * KDIM + kt * BK + ch * 8);
    }
#pragma unroll
    for (int p = 0; p < 4; p++) {
        int id = tid + p * NTHREADS;
        int row = id >> 3, ch = id & 7;
        uint32_t off = (uint32_t)row * 128 + (uint32_t)ch * 16;
        cp_async16(b_off + sw128(off),
                   gB + (size_t)row * KDIM + kt * BK + ch * 8);
    }
    cp_commit();
}

__global__ void __launch_bounds__(NTHREADS, 2)
gemm_kernel(const float* __restrict__ bias, float* __restrict__ out) {
    extern __shared__ char smem[];
    uint32_t sb = smem_to_u32(smem);
    int tid = threadIdx.x;
    int wid = tid >> 5, lane = tid & 31;
    int warp_m = wid >> 2;            // 0..1  (64 rows each)
    int warp_n = wid & 3;             // 0..3  (32 cols each)
    int nbase = blockIdx.x * BN;
    int mbase = blockIdx.y * BM;

    const __half* gA = g_xh + (size_t)mbase * KDIM;
    const __half* gB = g_wq + (size_t)nbase * KDIM;

    float acc[4][4][4];
#pragma unroll
    for (int i = 0; i < 4; i++)
#pragma unroll
        for (int j = 0; j < 4; j++)
#pragma unroll
            for (int r = 0; r < 4; r++) acc[i][j][r] = 0.f;

    // XOR swizzle iterator: address for chunk (ch0 + 2*kk) of a row is
    //   lane_base(row) ^ (kk << 5)     [bits disjoint, no carries]
    int a_row = warp_m * 64 + ((lane >> 3) & 1) * 8 + (lane & 7);
    int b_row = warp_n * 32 + ((lane >> 3) & 1) * 8 + (lane & 7);
    int ch0 = lane >> 4;              // 0..1
    uint32_t a_base0 = (uint32_t)a_row * 128 + 16u * (uint32_t)(ch0 ^ (a_row & 7));
    uint32_t b_base0 = (uint32_t)b_row * 128 + 16u * (uint32_t)(ch0 ^ (b_row & 7));

    // prologue: fill stages 0,1
    load_stage(sb, 0, 0, tid, gA, gB);
    load_stage(sb, 1, 1, tid, gA, gB);

    // A-fragment double buffer, pipelined ACROSS the per-kt barrier.
    uint32_t af[2][4][4];

    // wait for stage 0, prefetch kk=0 A-frags of stage 0 (before first barrier)
    cp_wait<1>();
    __syncthreads();
    {
        uint32_t a_base = sb + 0 * STAGE_BYTES + a_base0;
#pragma unroll
        for (int i = 0; i < 4; i++) ldsm4(af[0][i], a_base + i * 2048);
    }

    int cur = 0, nxt_s = 2;
    for (int kt = 0; kt < KT; kt++) {
        // stage (kt)%3 data is complete and its kk0 A-frags are in af[0].
        // Barrier: everyone done READING stage (kt-1)%3, which load below reuses.
        __syncthreads();

        int nxt = kt + STAGES - 1;
        if (nxt < KT) load_stage(sb, nxt_s, nxt, tid, gA, gB);
        else cp_commit();

        uint32_t a_base = sb + cur * STAGE_BYTES + a_base0;
        uint32_t b_base = sb + cur * STAGE_BYTES + A_STAGE_BYTES + b_base0;

#pragma unroll
        for (int kk = 0; kk < 4; kk++) {
            int c = kk & 1, n = c ^ 1;
            // B frags just-in-time (2 LDSM; short ramp hidden by MMA stream)
            uint32_t bf[2][4];
            uint32_t bx = b_base ^ (uint32_t)(kk << 5);
#pragma unroll
            for (int g = 0; g < 2; g++) ldsm4(bf[g], bx + g * 2048);
            if (kk < 3) {   // prefetch next kk's A-frags into the other buffer
                uint32_t ax = a_base ^ (uint32_t)((kk + 1) << 5);
#pragma unroll
                for (int i = 0; i < 4; i++) ldsm4(af[n][i], ax + i * 2048);
            }
#pragma unroll
            for (int i = 0; i < 4; i++)
#pragma unroll
                for (int j = 0; j < 4; j++)
                    mma16816(acc[i][j], af[c][i],
                             bf[j >> 1][j & 1], bf[j >> 1][(j & 1) + 2]);

            if (kk == 3 && kt + 1 < KT) {
                // cross-barrier prefetch: stage (kt+1)%3 is complete after
                // wait<1> (outstanding: only the group issued this iter).
                cp_wait<1>();
                int nc = (cur == STAGES - 1) ? 0 : cur + 1;
                uint32_t an = sb + nc * STAGE_BYTES + a_base0;
#pragma unroll
                for (int i = 0; i < 4; i++) ldsm4(af[0][i], an + i * 2048);
            }
        }

        cur = (cur == STAGES - 1) ? 0 : cur + 1;
        nxt_s = (nxt_s == STAGES - 1) ? 0 : nxt_s + 1;
    }

    // epilogue: direct to gmem with bias
    int m0 = mbase + warp_m * 64 + (lane >> 2);
    int n0 = nbase + warp_n * 32 + (lane & 3) * 2;
    float2 bj[4];
#pragma unroll
    for (int j = 0; j < 4; j++)
        bj[j] = *reinterpret_cast<const float2*>(bias + n0 + j * 8);
#pragma unroll
    for (int i = 0; i < 4; i++) {
        float* row_lo = out + (size_t)(m0 + i * 16) * ODIM;
        float* row_hi = out + (size_t)(m0 + i * 16 + 8) * ODIM;
#pragma unroll
        for (int j = 0; j < 4; j++) {
            float2 lo = { acc[i][j][0] + bj[j].x, acc[i][j][1] + bj[j].y };
            float2 hi = { acc[i][j][2] + bj[j].x, acc[i][j][3] + bj[j].y };
            *reinterpret_cast<float2*>(row_lo + n0 + j * 8) = lo;
            *reinterpret_cast<float2*>(row_hi + n0 + j * 8) = hi;
        }
    }
}

// ---------------- launch ----------------
extern "C" void kernel_launch(void* const* d_in, const int* in_sizes, int n_in,
                              void* d_out, int out_size) {
    const float* x     = (const float*)d_in[0];
    const float* w     = (const float*)d_in[1];
    const float* bias  = (const float*)d_in[2];
    const float* basis = (const float*)d_in[3];
    float* out = (float*)d_out;

    cudaFuncSetAttribute(gemm_kernel, cudaFuncAttributeMaxDynamicSharedMemorySize,
                         SMEM_TOTAL);

    prep_kernel<<<WBLKS + XBLKS, 256>>>(w, x, basis);
    gemm_kernel<<<dim3(ODIM / BN, TOKENS / BM), NTHREADS, SMEM_TOTAL>>>(bias, out);
}

// round 13
// speedup vs baseline: 1.4253x; 1.1605x over previous
#include <cuda_runtime.h>
#include <cuda_fp16.h>
#include <cstdint>
#include <cstddef>

// ---------------- problem constants ----------------
#define TOKENS 8192
#define KDIM   4096
#define ODIM   4096

#define BM 128
#define BN 128
#define BK 64
#define KT (KDIM / BK)      // 64 k-iterations
#define STAGES 3
#define NTHREADS 256        // 8 warps in 2x4, warp tile 64x32

#define A_STAGE_BYTES (BM * BK * 2)
#define B_STAGE_BYTES (BN * BK * 2)
#define STAGE_BYTES   (A_STAGE_BYTES + B_STAGE_BYTES)   // 32768
#define SMEM_TOTAL    (STAGES * STAGE_BYTES)            // 98304 -> 2 CTAs/SM

// ---------------- scratch (no runtime allocation allowed) ----------------
__device__ __half g_xh[(size_t)TOKENS * KDIM];   // 64 MB
__device__ __half g_wq[(size_t)ODIM * KDIM];     // 32 MB

// ---------------- helpers ----------------
__device__ __forceinline__ uint32_t smem_to_u32(const void* p) {
    uint32_t a;
    asm("{ .reg .u64 t; cvta.to.shared.u64 t, %1; cvt.u32.u64 %0, t; }" : "=r"(a) : "l"(p));
    return a;
}
__device__ __forceinline__ uint32_t sw128(uint32_t off) {
    return off ^ ((off >> 3) & 0x70);
}
__device__ __forceinline__ void cp_async16(uint32_t dst, const void* src) {
    asm volatile("cp.async.cg.shared.global [%0], [%1], 16;" :: "r"(dst), "l"(src));
}
__device__ __forceinline__ void cp_commit() {
    asm volatile("cp.async.commit_group;" ::: "memory");
}
template <int N>
__device__ __forceinline__ void cp_wait() {
    asm volatile("cp.async.wait_group %0;" :: "n"(N) : "memory");
}
__device__ __forceinline__ void ldsm4(uint32_t* r, uint32_t addr) {
    asm volatile("ldmatrix.sync.aligned.m8n8.x4.shared.b16 {%0,%1,%2,%3}, [%4];"
                 : "=r"(r[0]), "=r"(r[1]), "=r"(r[2]), "=r"(r[3]) : "r"(addr));
}
__device__ __forceinline__ void mma16816(float* c, const uint32_t* a,
                                         uint32_t b0, uint32_t b1) {
    asm volatile(
        "mma.sync.aligned.m16n8k16.row.col.f32.f16.f16.f32 "
        "{%0,%1,%2,%3}, {%4,%5,%6,%7}, {%8,%9}, {%0,%1,%2,%3};"
        : "+f"(c[0]), "+f"(c[1]), "+f"(c[2]), "+f"(c[3])
        : "r"(a[0]), "r"(a[1]), "r"(a[2]), "r"(a[3]), "r"(b0), "r"(b1));
}

// ---------------- fused prep kernel ----------------
// Quantizer: levels {±(L+S), ±(L−S)}, thresholds {−L, 0, L}
// => q = sgn(w) * (L + (|w| > L ? S : -S)).   (ILP = 2 float4 per thread)
#define W_N4   (ODIM * KDIM / 4)
#define X_N4   (TOKENS * KDIM / 4)
#define WBLKS  ((W_N4 / 2 + 255) / 256)
#define XBLKS  ((X_N4 / 2 + 255) / 256)

__global__ void prep_kernel(const float* __restrict__ w,
                            const float* __restrict__ x,
                            const float* __restrict__ basis) {
    int b = blockIdx.x;
    if (b < WBLKS) {
        float b0 = fabsf(basis[0]), b1 = fabsf(basis[1]);
        float L = fmaxf(b0, b1), S = fminf(b0, b1);
        int i0 = (b * blockDim.x + threadIdx.x) * 2;
#pragma unroll
        for (int u = 0; u < 2; u++) {
            int i = i0 + u;
            if (i >= W_N4) return;
            float4 v = reinterpret_cast<const float4*>(w)[i];
            float m0 = L + ((fabsf(v.x) > L) ? S : -S);
            float m1 = L + ((fabsf(v.y) > L) ? S : -S);
            float m2 = L + ((fabsf(v.z) > L) ? S : -S);
            float m3 = L + ((fabsf(v.w) > L) ? S : -S);
            __half2 p0 = __floats2half2_rn(copysignf(m0, v.x), copysignf(m1, v.y));
            __half2 p1 = __floats2half2_rn(copysignf(m2, v.z), copysignf(m3, v.w));
            uint2 o;
            o.x = *reinterpret_cast<uint32_t*>(&p0);
            o.y = *reinterpret_cast<uint32_t*>(&p1);
            reinterpret_cast<uint2*>(g_wq)[i] = o;
        }
    } else {
        int i0 = ((b - WBLKS) * blockDim.x + threadIdx.x) * 2;
#pragma unroll
        for (int u = 0; u < 2; u++) {
            int i = i0 + u;
            if (i >= X_N4) return;
            float4 v = reinterpret_cast<const float4*>(x)[i];
            __half2 a = __floats2half2_rn(v.x, v.y);
            __half2 c = __floats2half2_rn(v.z, v.w);
            uint2 o;
            o.x = *reinterpret_cast<uint32_t*>(&a);
            o.y = *reinterpret_cast<uint32_t*>(&c);
            reinterpret_cast<uint2*>(g_xh)[i] = o;
        }
    }
}

// ---------------- GEMM mainloop ----------------
__device__ __forceinline__ void load_stage(uint32_t sb, int s, int kt, int tid,
                                           const __half* gA, const __half* gB) {
    uint32_t a_off = sb + s * STAGE_BYTES;
    uint32_t b_off = a_off + A_STAGE_BYTES;
#pragma unroll
    for (int p = 0; p < 4; p++) {
        int id = tid + p * NTHREADS;
        int row = id >> 3, ch = id & 7;
        uint32_t off = (uint32_t)row * 128 + (uint32_t)ch * 16;
        cp_async16(a_off + sw128(off),
                   gA + (size_t)row * KDIM + kt * BK + ch * 8);
    }
#pragma unroll
    for (int p = 0; p < 4; p++) {
        int id = tid + p * NTHREADS;
        int row = id >> 3, ch = id & 7;
        uint32_t off = (uint32_t)row * 128 + (uint32_t)ch * 16;
        cp_async16(b_off + sw128(off),
                   gB + (size_t)row * KDIM + kt * BK + ch * 8);
    }
    cp_commit();
}

__global__ void __launch_bounds__(NTHREADS, 2)
gemm_kernel(const float* __restrict__ bias, float* __restrict__ out) {
    extern __shared__ char smem[];
    uint32_t sb = smem_to_u32(smem);
    int tid = threadIdx.x;
    int wid = tid >> 5, lane = tid & 31;
    int warp_m = wid >> 2;            // 0..1  (64 rows each)
    int warp_n = wid & 3;             // 0..3  (32 cols each)
    int nbase = blockIdx.x * BN;
    int mbase = blockIdx.y * BM;

    const __half* gA = g_xh + (size_t)mbase * KDIM;
    const __half* gB = g_wq + (size_t)nbase * KDIM;

    float acc[4][4][4];
#pragma unroll
    for (int i = 0; i < 4; i++)
#pragma unroll
        for (int j = 0; j < 4; j++)
#pragma unroll
            for (int r = 0; r < 4; r++) acc[i][j][r] = 0.f;

    // XOR swizzle iterator: address for chunk (ch0 + 2*kk) of a row is
    //   lane_base(row) ^ (kk << 5)     [bits disjoint, no carries]
    int a_row = warp_m * 64 + ((lane >> 3) & 1) * 8 + (lane & 7);
    int b_row = warp_n * 32 + ((lane >> 3) & 1) * 8 + (lane & 7);
    int ch0 = lane >> 4;              // 0..1
    uint32_t a_base0 = (uint32_t)a_row * 128 + 16u * (uint32_t)(ch0 ^ (a_row & 7));
    uint32_t b_base0 = (uint32_t)b_row * 128 + 16u * (uint32_t)(ch0 ^ (b_row & 7));

    // prologue: fill stages 0,1
    load_stage(sb, 0, 0, tid, gA, gB);
    load_stage(sb, 1, 1, tid, gA, gB);

    // fragment double buffers, kk0 pipelined ACROSS the per-kt barrier
    uint32_t af[2][4][4], bf[2][2][4];

    // wait for stage 0; prefetch kk=0 A+B frags BEFORE the first barrier
    cp_wait<1>();
    __syncthreads();
    {
        uint32_t a0 = sb + a_base0;
        uint32_t b0 = sb + A_STAGE_BYTES + b_base0;
#pragma unroll
        for (int i = 0; i < 4; i++) ldsm4(af[0][i], a0 + i * 2048);
#pragma unroll
        for (int g = 0; g < 2; g++) ldsm4(bf[0][g], b0 + g * 2048);
    }

    int cur = 0, nxt_s = 2;
    for (int kt = 0; kt < KT; kt++) {
        // stage kt%3 is complete and its kk0 frags are in af[0]/bf[0].
        __syncthreads();

        uint32_t a_base = sb + cur * STAGE_BYTES + a_base0;
        uint32_t b_base = sb + cur * STAGE_BYTES + A_STAGE_BYTES + b_base0;

        // prefetch kk=1 frags (covers LDS latency under kk0's MMA burst)
        {
            uint32_t ax = a_base ^ 32u, bx = b_base ^ 32u;
#pragma unroll
            for (int i = 0; i < 4; i++) ldsm4(af[1][i], ax + i * 2048);
#pragma unroll
            for (int g = 0; g < 2; g++) ldsm4(bf[1][g], bx + g * 2048);
        }

        // kk=0 MMA burst FIRST — tensor pipe starts immediately post-barrier
#pragma unroll
        for (int i = 0; i < 4; i++)
#pragma unroll
            for (int j = 0; j < 4; j++)
                mma16816(acc[i][j], af[0][i],
                         bf[0][j >> 1][j & 1], bf[0][j >> 1][(j & 1) + 2]);

        // cp.async burst issues while kk0 drains through the tensor pipe
        int nxt = kt + STAGES - 1;
        if (nxt < KT) load_stage(sb, nxt_s, nxt, tid, gA, gB);
        else cp_commit();

#pragma unroll
        for (int kk = 1; kk < 4; kk++) {
            int c = kk & 1;
            if (kk < 3) {   // prefetch kk+1 into the buffer kk just vacated
                uint32_t ax = a_base ^ (uint32_t)((kk + 1) << 5);
                uint32_t bx = b_base ^ (uint32_t)((kk + 1) << 5);
#pragma unroll
                for (int i = 0; i < 4; i++) ldsm4(af[c ^ 1][i], ax + i * 2048);
#pragma unroll
                for (int g = 0; g < 2; g++) ldsm4(bf[c ^ 1][g], bx + g * 2048);
            }
#pragma unroll
            for (int i = 0; i < 4; i++)
#pragma unroll
                for (int j = 0; j < 4; j++)
                    mma16816(acc[i][j], af[c][i],
                             bf[c][j >> 1][j & 1], bf[c][j >> 1][(j & 1) + 2]);

            if (kk == 3 && kt + 1 < KT) {
                // cross-barrier prefetch of next stage's kk0 frags:
                // after wait<1>, stage (kt+1)%3 is complete; its next
                // overwrite is 2 barriers away -> race-free.
                cp_wait<1>();
                int nc = (cur == STAGES - 1) ? 0 : cur + 1;
                uint32_t an = sb + nc * STAGE_BYTES + a_base0;
                uint32_t bn = sb + nc * STAGE_BYTES + A_STAGE_BYTES + b_base0;
#pragma unroll
                for (int i = 0; i < 4; i++) ldsm4(af[0][i], an + i * 2048);
#pragma unroll
                for (int g = 0; g < 2; g++) ldsm4(bf[0][g], bn + g * 2048);
            }
        }

        cur = (cur == STAGES - 1) ? 0 : cur + 1;
        nxt_s = (nxt_s == STAGES - 1) ? 0 : nxt_s + 1;
    }

    // epilogue: direct to gmem with bias
    int m0 = mbase + warp_m * 64 + (lane >> 2);
    int n0 = nbase + warp_n * 32 + (lane & 3) * 2;
    float2 bj[4];
#pragma unroll
    for (int j = 0; j < 4; j++)
        bj[j] = *reinterpret_cast<const float2*>(bias + n0 + j * 8);
#pragma unroll
    for (int i = 0; i < 4; i++) {
        float* row_lo = out + (size_t)(m0 + i * 16) * ODIM;
        float* row_hi = out + (size_t)(m0 + i * 16 + 8) * ODIM;
#pragma unroll
        for (int j = 0; j < 4; j++) {
            float2 lo = { acc[i][j][0] + bj[j].x, acc[i][j][1] + bj[j].y };
            float2 hi = { acc[i][j][2] + bj[j].x, acc[i][j][3] + bj[j].y };
            *reinterpret_cast<float2*>(row_lo + n0 + j * 8) = lo;
            *reinterpret_cast<float2*>(row_hi + n0 + j * 8) = hi;
        }
    }
}

// ---------------- launch ----------------
extern "C" void kernel_launch(void* const* d_in, const int* in_sizes, int n_in,
                              void* d_out, int out_size) {
    const float* x     = (const float*)d_in[0];
    const float* w     = (const float*)d_in[1];
    const float* bias  = (const float*)d_in[2];
    const float* basis = (const float*)d_in[3];
    float* out = (float*)d_out;

    cudaFuncSetAttribute(gemm_kernel, cudaFuncAttributeMaxDynamicSharedMemorySize,
                         SMEM_TOTAL);

    prep_kernel<<<WBLKS + XBLKS, 256>>>(w, x, basis);
    gemm_kernel<<<dim3(ODIM / BN, TOKENS / BM), NTHREADS, SMEM_TOTAL>>>(bias, out);
}